// round 5
// baseline (speedup 1.0000x reference)
#include <cuda_runtime.h>
#include <cuda_bf16.h>

// Problem constants (fixed by the reference setup)
constexpr int N    = 100000;   // nodes
constexpr int E    = 300000;   // directed edges
constexpr int ETOT = E + N;    // + self loops
constexpr int NG   = 4096;     // graphs
constexpr int HID  = 128;
constexpr int FIN  = 22;

// ---------------- scratch (device globals; no allocations allowed) ----------
__device__ float g_h[N * HID];      // transformed features h = A@W (per layer)
__device__ float g_out[N * HID];    // aggregated messages (per layer)
__device__ float g_als[N * 4];      // per-node src attention logits (H<=4)
__device__ float g_ald[N * 4];      // per-node dst attention logits
__device__ float g_ex[ETOT * 4];    // exp(leaky(e)) per edge per head
__device__ float g_den[N * 4];      // softmax denominators per dst per head
__device__ float g_bnsum[HID];
__device__ float g_bnsq[HID];
__device__ float g_pool[NG * HID];
__device__ float g_cnt[NG];

// ---------------- zero kernels ----------------------------------------------
__global__ void zero_layer_kernel() {
    int i = blockIdx.x * 256 + threadIdx.x;
    if (i < N * HID) g_out[i] = 0.f;
    if (i < N * 4)   g_den[i] = 0.f;
    if (i < HID) { g_bnsum[i] = 0.f; g_bnsq[i] = 0.f; }
}

__global__ void zero_pool_kernel() {
    int i = blockIdx.x * 256 + threadIdx.x;
    if (i < NG * HID) g_pool[i] = 0.f;
    if (i < NG)       g_cnt[i] = 0.f;
}

// ---------------- GEMM + fused attention projections ------------------------
// h = A[N,K] @ W[K,128]; al_s[n,head] = sum_c h[n,head*C+c]*a_s[head,c]
// Block: 128 threads (one per output feature), 4 nodes per block.
// SRC_GH: read input from the device-global g_h (in-kernel symbol reference —
// passing the __device__ symbol from HOST code passes the host shadow address,
// which on GB300/ATS silently reads zeros).
// Safe in-place for g_h: each block reads only its own 4 rows into shared
// before writing them back.
template<int K, int H, bool SRC_GH>
__global__ void gemm_att(const float* __restrict__ Aext, const float* __restrict__ W,
                         const float* __restrict__ a_s, const float* __restrict__ a_d)
{
    constexpr int NPB = 4;
    __shared__ float sA[NPB * K];
    __shared__ float sredS[NPB][4];
    __shared__ float sredD[NPB][4];

    const float* A = SRC_GH ? (const float*)g_h : Aext;

    const int n0 = blockIdx.x * NPB;
    const int f  = threadIdx.x;

    for (int i = f; i < NPB * K; i += 128) {
        int t = i / K, k = i - t * K;
        sA[i] = A[(long)(n0 + t) * K + k];
    }
    __syncthreads();

    float acc[NPB] = {0.f, 0.f, 0.f, 0.f};
#pragma unroll 4
    for (int k = 0; k < K; k++) {
        float w = W[k * HID + f];
#pragma unroll
        for (int t = 0; t < NPB; t++) acc[t] += sA[t * K + k] * w;
    }

    const float as_f = a_s[f];
    const float ad_f = a_d[f];
    const int warp = f >> 5, lane = f & 31;

#pragma unroll
    for (int t = 0; t < NPB; t++) {
        g_h[(long)(n0 + t) * HID + f] = acc[t];
        float vs = acc[t] * as_f;
        float vd = acc[t] * ad_f;
#pragma unroll
        for (int o = 16; o; o >>= 1) {
            vs += __shfl_down_sync(0xFFFFFFFFu, vs, o);
            vd += __shfl_down_sync(0xFFFFFFFFu, vd, o);
        }
        if (lane == 0) { sredS[t][warp] = vs; sredD[t][warp] = vd; }
    }
    __syncthreads();

    if (H == 4) {
        if (f < 16) {
            int t = f >> 2, w = f & 3;
            g_als[(n0 + t) * 4 + w] = sredS[t][w];
            g_ald[(n0 + t) * 4 + w] = sredD[t][w];
        }
    } else { // H == 1
        if (f < NPB) {
            float s = 0.f, d = 0.f;
#pragma unroll
            for (int w = 0; w < 4; w++) { s += sredS[f][w]; d += sredD[f][w]; }
            g_als[n0 + f] = s;
            g_ald[n0 + f] = d;
        }
    }
}

// ---------------- per-edge attention logits + softmax denominators ----------
// segment_max skipped: softmax is shift-invariant; logits are O(1) so exp is safe.
template<int H>
__global__ void edge_att(const int* __restrict__ ei)
{
    int idx = blockIdx.x * 256 + threadIdx.x;
    if (idx >= ETOT * H) return;
    int e = idx / H, hh = idx - e * H;
    int s, d;
    if (e < E) { s = ei[e]; d = ei[E + e]; }
    else       { s = d = e - E; }                // self loop
    float x = g_als[s * H + hh] + g_ald[d * H + hh];
    float l = x > 0.f ? x : 0.2f * x;            // leaky_relu(0.2)
    float ex = expf(l);
    g_ex[idx] = ex;
    atomicAdd(&g_den[d * H + hh], ex);
}

// ---------------- message aggregation: out[dst] += alpha * h[src] -----------
// One thread per (edge, 4 features): float4 gather of h[src], 4 scatter-adds.
template<int H>
__global__ void edge_aggr(const int* __restrict__ ei)
{
    int idx = blockIdx.x * 256 + threadIdx.x;          // ETOT * 32 threads
    if (idx >= ETOT * 32) return;
    int e = idx >> 5, q = idx & 31;                    // q: which float4 (0..31)
    int f = q << 2;                                    // feature base
    int s, d;
    if (e < E) { s = ei[e]; d = ei[E + e]; }
    else       { s = d = e - E; }
    int hh = (H == 4) ? (f >> 5) : 0;
    float alpha = g_ex[e * H + hh] / (g_den[d * H + hh] + 1e-16f);
    float4 hv = *(const float4*)&g_h[(long)s * HID + f];
    float* o = &g_out[(long)d * HID + f];
    atomicAdd(o + 0, hv.x * alpha);
    atomicAdd(o + 1, hv.y * alpha);
    atomicAdd(o + 2, hv.z * alpha);
    atomicAdd(o + 3, hv.w * alpha);
}

// ---------------- BatchNorm stats (two-stage reduction) ---------------------
constexpr int BN_CHUNK = 500;   // 200 blocks * 500 nodes = N
__global__ void bn_stats()
{
    int f  = threadIdx.x;              // 128 threads, one per feature
    int n0 = blockIdx.x * BN_CHUNK;
    float s = 0.f, q = 0.f;
    for (int i = 0; i < BN_CHUNK; i++) {
        float v = g_out[(long)(n0 + i) * HID + f];
        s += v; q += v * v;
    }
    atomicAdd(&g_bnsum[f], s);
    atomicAdd(&g_bnsq[f], q);
}

// Apply BN (+gamma,beta) + ReLU; writes activation into g_h (next layer input).
// Note: the GAT bias b cancels exactly through BN, so it was never added.
__global__ void bn_apply(const float* __restrict__ gma, const float* __restrict__ bta)
{
    int idx = blockIdx.x * 256 + threadIdx.x;
    if (idx >= N * HID) return;
    int f = idx & 127;
    float m   = g_bnsum[f] * (1.0f / N);
    float var = g_bnsq[f] * (1.0f / N) - m * m;
    float y = (g_out[idx] - m) * rsqrtf(var + 1e-5f) * gma[f] + bta[f];
    g_h[idx] = y > 0.f ? y : 0.f;
}

// ---------------- global mean pool ------------------------------------------
__global__ void pool_cnt(const int* __restrict__ batch)
{
    int n = blockIdx.x * 256 + threadIdx.x;
    if (n < N) atomicAdd(&g_cnt[batch[n]], 1.f);
}

__global__ void pool_sum(const int* __restrict__ batch)
{
    int idx = blockIdx.x * 256 + threadIdx.x;
    if (idx >= N * HID) return;
    int n = idx >> 7, f = idx & 127;
    atomicAdd(&g_pool[(long)batch[n] * HID + f], g_h[idx]);
}

// ---------------- MLP head: relu(pooled@fw1+fb1)@fw2+fb2 --------------------
__global__ void mlp_head(const float* __restrict__ fw1, const float* __restrict__ fb1,
                         const float* __restrict__ fw2, const float* __restrict__ fb2,
                         float* __restrict__ out)
{
    __shared__ float ph[HID];
    __shared__ float part[2];
    int g = blockIdx.x, j = threadIdx.x;       // 64 threads
    float c = g_cnt[g];
    float inv = 1.f / (c < 1.f ? 1.f : c);
    ph[j]      = g_pool[g * HID + j] * inv;
    ph[j + 64] = g_pool[g * HID + 64 + j] * inv;
    __syncthreads();

    float acc = fb1[j];
#pragma unroll
    for (int k = 0; k < HID; k++) acc += ph[k] * fw1[k * 64 + j];
    float z = acc > 0.f ? acc : 0.f;
    float p = z * fw2[j];
#pragma unroll
    for (int o = 16; o; o >>= 1) p += __shfl_down_sync(0xFFFFFFFFu, p, o);
    if ((j & 31) == 0) part[j >> 5] = p;
    __syncthreads();
    if (j == 0) out[g] = part[0] + part[1] + fb2[0];
}

// ---------------- host driver ------------------------------------------------
extern "C" void kernel_launch(void* const* d_in, const int* in_sizes, int n_in,
                              void* d_out, int out_size)
{
    const float* x     = (const float*)d_in[0];
    const int*   ei    = (const int*)  d_in[1];
    const int*   batch = (const int*)  d_in[2];
    const float* W1  = (const float*)d_in[3];
    const float* as1 = (const float*)d_in[4];
    const float* ad1 = (const float*)d_in[5];
    const float* g1  = (const float*)d_in[7];
    const float* be1 = (const float*)d_in[8];
    const float* W2  = (const float*)d_in[9];
    const float* as2 = (const float*)d_in[10];
    const float* ad2 = (const float*)d_in[11];
    const float* g2  = (const float*)d_in[13];
    const float* be2 = (const float*)d_in[14];
    const float* W3  = (const float*)d_in[15];
    const float* as3 = (const float*)d_in[16];
    const float* ad3 = (const float*)d_in[17];
    const float* g3  = (const float*)d_in[19];
    const float* be3 = (const float*)d_in[20];
    const float* fw1 = (const float*)d_in[21];
    const float* fb1 = (const float*)d_in[22];
    const float* fw2 = (const float*)d_in[23];
    const float* fb2 = (const float*)d_in[24];
    float* out = (float*)d_out;

    const int ZL_GRID   = (N * HID + 255) / 256;        // 50000
    const int GEMM_GRID = N / 4;                        // 25000
    const int EA4_GRID  = (ETOT * 4 + 255) / 256;
    const int EA1_GRID  = (ETOT * 1 + 255) / 256;
    const int AGG_GRID  = (ETOT * 32 + 255) / 256;      // 50000
    const int BNA_GRID  = (N * HID + 255) / 256;
    const int BNS_GRID  = N / BN_CHUNK;                 // 200

    // ---- Layer 1: 22 -> 4x32  (input from harness buffer x)
    zero_layer_kernel<<<ZL_GRID, 256>>>();
    gemm_att<FIN, 4, false><<<GEMM_GRID, 128>>>(x, W1, as1, ad1);
    edge_att<4><<<EA4_GRID, 256>>>(ei);
    edge_aggr<4><<<AGG_GRID, 256>>>(ei);
    bn_stats<<<BNS_GRID, 128>>>();
    bn_apply<<<BNA_GRID, 256>>>(g1, be1);

    // ---- Layer 2: 128 -> 4x32  (input from g_h via in-kernel symbol)
    zero_layer_kernel<<<ZL_GRID, 256>>>();
    gemm_att<HID, 4, true><<<GEMM_GRID, 128>>>(nullptr, W2, as2, ad2);
    edge_att<4><<<EA4_GRID, 256>>>(ei);
    edge_aggr<4><<<AGG_GRID, 256>>>(ei);
    bn_stats<<<BNS_GRID, 128>>>();
    bn_apply<<<BNA_GRID, 256>>>(g2, be2);

    // ---- Layer 3: 128 -> 1x128
    zero_layer_kernel<<<ZL_GRID, 256>>>();
    gemm_att<HID, 1, true><<<GEMM_GRID, 128>>>(nullptr, W3, as3, ad3);
    edge_att<1><<<EA1_GRID, 256>>>(ei);
    edge_aggr<1><<<AGG_GRID, 256>>>(ei);
    bn_stats<<<BNS_GRID, 128>>>();
    bn_apply<<<BNA_GRID, 256>>>(g3, be3);

    // ---- Pool + MLP head
    zero_pool_kernel<<<(NG * HID + 255) / 256, 256>>>();
    pool_cnt<<<(N + 255) / 256, 256>>>(batch);
    pool_sum<<<(N * HID + 255) / 256, 256>>>(batch);
    mlp_head<<<NG, 64>>>(fw1, fb1, fw2, fb2, out);
}